// round 3
// baseline (speedup 1.0000x reference)
#include <cuda_runtime.h>

#define BATCH   512
#define FCIN    4096
#define EMBED   1024
#define NASPECT 2000
#define NBRANDS 10000

// Scratch (no cudaMalloc allowed).
__device__ float g_H[BATCH * FCIN];   // lrelu(image@W1+b1)
__device__ float g_F[BATCH * EMBED];  // g_H@W2+b2
__device__ float g_V[BATCH * EMBED];  // gather(brand_emb)@aspects

// ---------------------------------------------------------------------------
// GEMM1: g_H = lrelu(image[512,4096] @ W1[4096,4096] + b1)
// 128x128x16 tile, 256 threads, 8x8 microtile. Grid (32, 4) = 128 CTAs.
// ---------------------------------------------------------------------------
__global__ void __launch_bounds__(256, 2)
gemm1_kernel(const float* __restrict__ A, const float* __restrict__ Bm,
             const float* __restrict__ bias)
{
    __shared__ float As[16][128];
    __shared__ float Bs[16][128];

    const int tid = threadIdx.x;
    const int bx = blockIdx.x, by = blockIdx.y;
    const int tx = tid & 15;       // column group 0..15
    const int ty = tid >> 4;       // row group 0..15
    const int N = FCIN, K = FCIN;

    // A-tile: 128 rows x 16 cols -> 8 floats (2 x float4) per thread
    const int arow = tid >> 1;           // 0..127
    const int acol = (tid & 1) * 8;      // 0 or 8
    // B-tile: 16 rows x 128 cols -> 8 floats (2 x float4) per thread
    const int brow = tid >> 4;           // 0..15
    const int bcol = (tid & 15) * 8;     // 0..120

    const float* Arow = A + (size_t)(by * 128 + arow) * K;
    const float* Bb   = Bm + (size_t)(bx * 128);

    float acc[8][8];
    #pragma unroll
    for (int i = 0; i < 8; i++)
        #pragma unroll
        for (int j = 0; j < 8; j++) acc[i][j] = 0.f;

    for (int k0 = 0; k0 < K; k0 += 16) {
        float4 a0 = *(const float4*)(Arow + k0 + acol);
        float4 a1 = *(const float4*)(Arow + k0 + acol + 4);
        As[acol + 0][arow] = a0.x;  As[acol + 1][arow] = a0.y;
        As[acol + 2][arow] = a0.z;  As[acol + 3][arow] = a0.w;
        As[acol + 4][arow] = a1.x;  As[acol + 5][arow] = a1.y;
        As[acol + 6][arow] = a1.z;  As[acol + 7][arow] = a1.w;
        const float* brd = Bb + (size_t)(k0 + brow) * N + bcol;
        *(float4*)&Bs[brow][bcol]     = *(const float4*)(brd);
        *(float4*)&Bs[brow][bcol + 4] = *(const float4*)(brd + 4);
        __syncthreads();

        #pragma unroll
        for (int kk = 0; kk < 16; kk++) {
            float af[8], bf[8];
            *(float4*)&af[0] = *(const float4*)&As[kk][ty * 8];
            *(float4*)&af[4] = *(const float4*)&As[kk][ty * 8 + 4];
            *(float4*)&bf[0] = *(const float4*)&Bs[kk][tx * 8];
            *(float4*)&bf[4] = *(const float4*)&Bs[kk][tx * 8 + 4];
            #pragma unroll
            for (int i = 0; i < 8; i++)
                #pragma unroll
                for (int j = 0; j < 8; j++)
                    acc[i][j] = fmaf(af[i], bf[j], acc[i][j]);
        }
        __syncthreads();
    }

    const int crow0 = by * 128 + ty * 8;
    const int ccol0 = bx * 128 + tx * 8;
    #pragma unroll
    for (int i = 0; i < 8; i++) {
        #pragma unroll
        for (int j = 0; j < 8; j++) {
            float v = acc[i][j] + bias[ccol0 + j];
            v = v > 0.f ? v : 0.01f * v;
            g_H[(size_t)(crow0 + i) * N + ccol0 + j] = v;
        }
    }
}

// ---------------------------------------------------------------------------
// 64x64x16 SGEMM, 256 threads, 4x4 microtile. Grid (16, 8) = 128 CTAs.
// GATHER: A-row r comes from A[rowidx[r]] (GEMM3, int32 indices, clamped).
// BIAS: add bias (GEMM2).
// ---------------------------------------------------------------------------
template<bool GATHER, bool BIAS>
__global__ void __launch_bounds__(256, 4)
sgemm64(const float* __restrict__ A, const float* __restrict__ Bm,
        const float* __restrict__ bias, float* __restrict__ C,
        int K, const int* __restrict__ rowidx)
{
    __shared__ float As[16][64];
    __shared__ float Bs[16][64];

    const int tid = threadIdx.x;
    const int bx = blockIdx.x, by = blockIdx.y;
    const int tx = tid & 15;
    const int ty = tid >> 4;
    const int N = EMBED;

    // A-tile: 64 rows x 16 cols -> 4 floats per thread
    const int arow = tid >> 2;           // 0..63
    const int acol = (tid & 3) * 4;      // 0,4,8,12
    // B-tile: 16 rows x 64 cols -> 4 floats per thread
    const int brow = tid >> 4;           // 0..15
    const int bcol = (tid & 15) * 4;     // 0..60

    int asrc = by * 64 + arow;
    if (GATHER) {
        asrc = rowidx[by * 64 + arow];
        // Defensive clamp: if index dtype assumption is ever wrong we get a
        // wrong (diagnosable) answer instead of an illegal access.
        asrc = asrc < 0 ? 0 : (asrc >= NBRANDS ? NBRANDS - 1 : asrc);
    }
    const float* Arow = A + (size_t)asrc * K;
    const float* Bb   = Bm + (size_t)(bx * 64);

    float acc[4][4];
    #pragma unroll
    for (int i = 0; i < 4; i++)
        #pragma unroll
        for (int j = 0; j < 4; j++) acc[i][j] = 0.f;

    for (int k0 = 0; k0 < K; k0 += 16) {
        float4 av = *(const float4*)(Arow + k0 + acol);
        As[acol + 0][arow] = av.x;
        As[acol + 1][arow] = av.y;
        As[acol + 2][arow] = av.z;
        As[acol + 3][arow] = av.w;
        *(float4*)&Bs[brow][bcol] =
            *(const float4*)(Bb + (size_t)(k0 + brow) * N + bcol);
        __syncthreads();

        #pragma unroll
        for (int kk = 0; kk < 16; kk++) {
            float af[4], bf[4];
            *(float4*)&af[0] = *(const float4*)&As[kk][ty * 4];
            *(float4*)&bf[0] = *(const float4*)&Bs[kk][tx * 4];
            #pragma unroll
            for (int i = 0; i < 4; i++)
                #pragma unroll
                for (int j = 0; j < 4; j++)
                    acc[i][j] = fmaf(af[i], bf[j], acc[i][j]);
        }
        __syncthreads();
    }

    const int crow0 = by * 64 + ty * 4;
    const int ccol0 = bx * 64 + tx * 4;
    #pragma unroll
    for (int i = 0; i < 4; i++) {
        #pragma unroll
        for (int j = 0; j < 4; j++) {
            float v = acc[i][j];
            if (BIAS) v += bias[ccol0 + j];
            C[(size_t)(crow0 + i) * N + ccol0 + j] = v;
        }
    }
}

// ---------------------------------------------------------------------------
// out[b] = dot(g_F[b,:], g_V[b,:]) / NASPECT
// ---------------------------------------------------------------------------
__global__ void __launch_bounds__(256)
final_dot(float* __restrict__ out)
{
    const int b = blockIdx.x;
    const float* f = g_F + (size_t)b * EMBED;
    const float* v = g_V + (size_t)b * EMBED;
    float s = 0.f;
    for (int i = threadIdx.x; i < EMBED; i += 256)
        s = fmaf(f[i], v[i], s);
    #pragma unroll
    for (int off = 16; off > 0; off >>= 1)
        s += __shfl_xor_sync(0xFFFFFFFFu, s, off);
    __shared__ float red[8];
    if ((threadIdx.x & 31) == 0) red[threadIdx.x >> 5] = s;
    __syncthreads();
    if (threadIdx.x < 8) {
        s = red[threadIdx.x];
        #pragma unroll
        for (int off = 4; off > 0; off >>= 1)
            s += __shfl_xor_sync(0xFFu, s, off);
        if (threadIdx.x == 0) out[b] = s * (1.0f / (float)NASPECT);
    }
}

extern "C" void kernel_launch(void* const* d_in, const int* in_sizes, int n_in,
                              void* d_out, int out_size)
{
    const float* image     = (const float*)d_in[0];
    const int*   brand     = (const int*)d_in[1];    // JAX x64 disabled -> int32
    const float* W1        = (const float*)d_in[2];
    const float* b1        = (const float*)d_in[3];
    const float* W2        = (const float*)d_in[4];
    const float* b2        = (const float*)d_in[5];
    const float* brand_emb = (const float*)d_in[6];
    const float* aspects   = (const float*)d_in[7];
    float*       out       = (float*)d_out;

    static float* pH = nullptr;
    static float* pF = nullptr;
    static float* pV = nullptr;
    if (!pH) {
        cudaGetSymbolAddress((void**)&pH, g_H);
        cudaGetSymbolAddress((void**)&pF, g_F);
        cudaGetSymbolAddress((void**)&pV, g_V);
    }

    // GEMM1: g_H = lrelu(image @ W1 + b1)   [512 x 4096], K=4096
    gemm1_kernel<<<dim3(FCIN / 128, BATCH / 128), 256>>>(image, W1, b1);

    // GEMM3: g_V = brand_emb[brand] @ aspects   [512 x 1024], K=2000
    sgemm64<true, false><<<dim3(EMBED / 64, BATCH / 64), 256>>>(
        brand_emb, aspects, nullptr, pV, NASPECT, brand);

    // GEMM2: g_F = g_H @ W2 + b2   [512 x 1024], K=4096
    sgemm64<false, true><<<dim3(EMBED / 64, BATCH / 64), 256>>>(
        pH, W2, b2, pF, FCIN, nullptr);

    // out[b] = dot(g_F[b], g_V[b]) / 2000
    final_dot<<<BATCH, 256>>>(out);
}

// round 6
// speedup vs baseline: 2.9981x; 2.9981x over previous
#include <cuda_runtime.h>
#include <cuda_bf16.h>
#include <cstdint>

#define BATCH   512
#define FCIN    4096
#define EMBED   1024
#define NASPECT 2000
#define NASPAD  2048
#define NBRANDS 10000

// ---------------------------------------------------------------------------
// Scratch (__device__ globals; no cudaMalloc allowed)
// ---------------------------------------------------------------------------
__device__ __align__(256) __nv_bfloat16 g_imgH[BATCH * FCIN];
__device__ __align__(256) __nv_bfloat16 g_imgL[BATCH * FCIN];
__device__ __align__(256) __nv_bfloat16 g_W1TH[FCIN * FCIN];
__device__ __align__(256) __nv_bfloat16 g_W1TL[FCIN * FCIN];
__device__ __align__(256) __nv_bfloat16 g_HH[BATCH * FCIN];
__device__ __align__(256) __nv_bfloat16 g_HL[BATCH * FCIN];
__device__ __align__(256) __nv_bfloat16 g_W2TH[EMBED * FCIN];
__device__ __align__(256) __nv_bfloat16 g_W2TL[EMBED * FCIN];
__device__ __align__(256) __nv_bfloat16 g_GH[BATCH * NASPAD];
__device__ __align__(256) __nv_bfloat16 g_GL[BATCH * NASPAD];
__device__ __align__(256) __nv_bfloat16 g_ATH[EMBED * NASPAD];
__device__ __align__(256) __nv_bfloat16 g_ATL[EMBED * NASPAD];
__device__ __align__(256) float g_F[BATCH * EMBED];
__device__ __align__(256) float g_V[BATCH * EMBED];

// ---------------------------------------------------------------------------
// sm_80-era PTX helpers (compile for plain sm_100; run on Blackwell legacy HMMA)
// ---------------------------------------------------------------------------
__device__ __forceinline__ uint32_t smem_u32(const void* p) {
    uint32_t a;
    asm("{ .reg .u64 t; cvta.to.shared.u64 t, %1; cvt.u32.u64 %0, t; }"
        : "=r"(a) : "l"(p));
    return a;
}
__device__ __forceinline__ void ldsm4(uint32_t* r, uint32_t addr) {
    asm volatile("ldmatrix.sync.aligned.m8n8.x4.shared.b16 {%0,%1,%2,%3}, [%4];"
        : "=r"(r[0]), "=r"(r[1]), "=r"(r[2]), "=r"(r[3]) : "r"(addr));
}
__device__ __forceinline__ void ldsm2(uint32_t* r, uint32_t addr) {
    asm volatile("ldmatrix.sync.aligned.m8n8.x2.shared.b16 {%0,%1}, [%2];"
        : "=r"(r[0]), "=r"(r[1]) : "r"(addr));
}
__device__ __forceinline__ void mma_bf16(float* d, const uint32_t* a, const uint32_t* b) {
    asm volatile("mma.sync.aligned.m16n8k16.row.col.f32.bf16.bf16.f32 "
        "{%0,%1,%2,%3}, {%4,%5,%6,%7}, {%8,%9}, {%0,%1,%2,%3};"
        : "+f"(d[0]), "+f"(d[1]), "+f"(d[2]), "+f"(d[3])
        : "r"(a[0]), "r"(a[1]), "r"(a[2]), "r"(a[3]), "r"(b[0]), "r"(b[1]));
}
__device__ __forceinline__ void cpa16(uint32_t d, const void* s) {
    asm volatile("cp.async.cg.shared.global [%0], [%1], 16;" :: "r"(d), "l"(s));
}
#define CPA_COMMIT() asm volatile("cp.async.commit_group;" ::: "memory")
#define CPA_WAIT(n)  asm volatile("cp.async.wait_group %0;" :: "n"(n) : "memory")

__device__ __forceinline__ void split2(float x, __nv_bfloat16& h, __nv_bfloat16& l) {
    h = __float2bfloat16(x);
    l = __float2bfloat16(x - __bfloat162float(h));
}
__device__ __forceinline__ uint32_t pack_bf16(__nv_bfloat16 a, __nv_bfloat16 b) {
    return (uint32_t)*(uint16_t*)&a | ((uint32_t)*(uint16_t*)&b << 16);
}

// ---------------------------------------------------------------------------
// bf16 3-MMA split GEMM on mma.sync (m16n8k16):
//   C = Ah·Bh^T + Ah·Bl^T + Al·Bh^T
// A: [M,K] row-major bf16 (hi/lo). B: [N,K] row-major bf16 (hi/lo).
// CTA tile BM x BN, K-chunk BK=64, 8 warps arranged (BM/WM) x (BN/WN).
// cp.async double-buffered smem; +8 bf16 row padding -> conflict-free ldmatrix.
// EPI: 0 = +bias, lrelu, write bf16 hi/lo; 1 = +bias fp32; 2 = fp32.
// ---------------------------------------------------------------------------
template<int BM, int BN, int BK, int WM, int WN, int EPI>
__global__ void __launch_bounds__(256)
gemm_mma(const __nv_bfloat16* __restrict__ Ah, const __nv_bfloat16* __restrict__ Al,
         const __nv_bfloat16* __restrict__ Bh, const __nv_bfloat16* __restrict__ Bl,
         const float* __restrict__ bias, int K, int ldc,
         float* __restrict__ Cf, __nv_bfloat16* __restrict__ Ch,
         __nv_bfloat16* __restrict__ Cl)
{
    constexpr int STRIDE = BK + 8;                 // bf16 elems per smem row
    constexpr int S2 = STRIDE * 2;                 // bytes per smem row
    constexpr int OFF_AH = 0;
    constexpr int OFF_AL = BM * S2;
    constexpr int OFF_BH = 2 * BM * S2;
    constexpr int OFF_BL = 2 * BM * S2 + BN * S2;
    constexpr int BUFB = (2 * BM + 2 * BN) * S2;   // one pipeline stage
    constexpr int MI = WM / 16, NI = WN / 8;
    constexpr int KS = BK / 16;
    constexpr int BK8 = BK / 8;                    // 16B chunks per row

    extern __shared__ __align__(128) char smem[];
    const uint32_t sb = smem_u32(smem);
    const int tid = threadIdx.x, wid = tid >> 5, lane = tid & 31;
    const int wm = wid % (BM / WM), wn = wid / (BM / WM);
    const int rowbase = blockIdx.y * BM, colbase = blockIdx.x * BN;

    const __nv_bfloat16* srcA[2] = { Ah + (size_t)rowbase * K, Al + (size_t)rowbase * K };
    const __nv_bfloat16* srcB[2] = { Bh + (size_t)colbase * K, Bl + (size_t)colbase * K };

    float acc[MI][NI][4];
    #pragma unroll
    for (int i = 0; i < MI; i++)
        #pragma unroll
        for (int j = 0; j < NI; j++)
            #pragma unroll
            for (int q = 0; q < 4; q++) acc[i][j][q] = 0.f;

    // per-thread ldmatrix base byte offsets within a tile
    const uint32_t aBase = (uint32_t)(((wm * WM + (lane & 15)) * STRIDE + (lane >> 4) * 8) * 2);
    const uint32_t bBase = (uint32_t)(((wn * WN + (lane & 7)) * STRIDE + ((lane >> 3) & 1) * 8) * 2);

    auto prefetch = [&](int chunk, int p) {
        const uint32_t tb = sb + p * BUFB;
        const int k0 = chunk * BK;
        #pragma unroll
        for (int i = tid; i < BM * BK8; i += 256) {     // A hi + lo
            int r = i / BK8, c = i % BK8;
            uint32_t d = (uint32_t)(r * S2 + c * 16);
            cpa16(tb + OFF_AH + d, srcA[0] + (size_t)r * K + k0 + c * 8);
            cpa16(tb + OFF_AL + d, srcA[1] + (size_t)r * K + k0 + c * 8);
        }
        #pragma unroll
        for (int i = tid; i < BN * BK8; i += 256) {     // B hi + lo
            int r = i / BK8, c = i % BK8;
            uint32_t d = (uint32_t)(r * S2 + c * 16);
            cpa16(tb + OFF_BH + d, srcB[0] + (size_t)r * K + k0 + c * 8);
            cpa16(tb + OFF_BL + d, srcB[1] + (size_t)r * K + k0 + c * 8);
        }
        CPA_COMMIT();
    };

    const int NC = K / BK;
    prefetch(0, 0);

    for (int c = 0; c < NC; c++) {
        const int p = c & 1;
        if (c + 1 < NC) { prefetch(c + 1, (c + 1) & 1); CPA_WAIT(1); }
        else            { CPA_WAIT(0); }
        __syncthreads();

        const uint32_t tb = sb + p * BUFB;
        #pragma unroll
        for (int ks = 0; ks < KS; ks++) {
            uint32_t aH[MI][4], aL[MI][4], bH[NI][2], bL[NI][2];
            #pragma unroll
            for (int mi = 0; mi < MI; mi++) {
                uint32_t o = aBase + (uint32_t)((mi * 16 * STRIDE + ks * 16) * 2);
                ldsm4(aH[mi], tb + OFF_AH + o);
                ldsm4(aL[mi], tb + OFF_AL + o);
            }
            #pragma unroll
            for (int ni = 0; ni < NI; ni++) {
                uint32_t o = bBase + (uint32_t)((ni * 8 * STRIDE + ks * 16) * 2);
                ldsm2(bH[ni], tb + OFF_BH + o);
                ldsm2(bL[ni], tb + OFF_BL + o);
            }
            #pragma unroll
            for (int mi = 0; mi < MI; mi++)
                #pragma unroll
                for (int ni = 0; ni < NI; ni++) {
                    mma_bf16(acc[mi][ni], aH[mi], bH[ni]);
                    mma_bf16(acc[mi][ni], aH[mi], bL[ni]);
                    mma_bf16(acc[mi][ni], aL[mi], bH[ni]);
                }
        }
        __syncthreads();
    }

    // Epilogue. Fragment element map: d0,d1 -> row lane>>2, cols (lane&3)*2,+1;
    // d2,d3 -> row (lane>>2)+8.
    const int r0 = rowbase + wm * WM + (lane >> 2);
    const int c0 = colbase + wn * WN + (lane & 3) * 2;
    #pragma unroll
    for (int mi = 0; mi < MI; mi++) {
        #pragma unroll
        for (int ni = 0; ni < NI; ni++) {
            const int cc = c0 + ni * 8;
            float b0 = 0.f, b1 = 0.f;
            if (EPI == 0 || EPI == 1) { b0 = __ldg(&bias[cc]); b1 = __ldg(&bias[cc + 1]); }
            #pragma unroll
            for (int h = 0; h < 2; h++) {
                const int rr = r0 + mi * 16 + h * 8;
                float v0 = acc[mi][ni][2 * h]     + b0;
                float v1 = acc[mi][ni][2 * h + 1] + b1;
                if (EPI == 0) {
                    v0 = v0 > 0.f ? v0 : 0.01f * v0;
                    v1 = v1 > 0.f ? v1 : 0.01f * v1;
                    __nv_bfloat16 h0, l0, h1, l1;
                    split2(v0, h0, l0); split2(v1, h1, l1);
                    *(uint32_t*)(Ch + (size_t)rr * ldc + cc) = pack_bf16(h0, h1);
                    *(uint32_t*)(Cl + (size_t)rr * ldc + cc) = pack_bf16(l0, l1);
                } else {
                    *(float2*)(Cf + (size_t)rr * ldc + cc) = make_float2(v0, v1);
                }
            }
        }
    }
}

// ---------------------------------------------------------------------------
// Conversion kernels (unchanged from R4 — these compiled fine)
// ---------------------------------------------------------------------------
__global__ void __launch_bounds__(256)
split_kernel(const float* __restrict__ in, __nv_bfloat16* __restrict__ hi,
             __nv_bfloat16* __restrict__ lo, int n4)
{
    int i = blockIdx.x * 256 + threadIdx.x;
    if (i >= n4) return;
    float4 v = ((const float4*)in)[i];
    __nv_bfloat16 h[4], l[4];
    split2(v.x, h[0], l[0]); split2(v.y, h[1], l[1]);
    split2(v.z, h[2], l[2]); split2(v.w, h[3], l[3]);
    ((uint2*)hi)[i] = make_uint2(pack_bf16(h[0], h[1]), pack_bf16(h[2], h[3]));
    ((uint2*)lo)[i] = make_uint2(pack_bf16(l[0], l[1]), pack_bf16(l[2], l[3]));
}

// Transpose + split: in[R,C] fp32 -> out[C,Rpad] bf16 hi/lo (pad rows>=R -> 0)
__global__ void __launch_bounds__(256)
transpose_split(const float* __restrict__ in, int R, int C, int Rpad,
                __nv_bfloat16* __restrict__ hi, __nv_bfloat16* __restrict__ lo)
{
    __shared__ float t[32][33];
    const int kb = blockIdx.x * 32, cb = blockIdx.y * 32;
    #pragma unroll
    for (int i = 0; i < 4; i++) {
        int k = kb + threadIdx.y + i * 8;
        float v = 0.f;
        if (k < R && cb + (int)threadIdx.x < C)
            v = in[(size_t)k * C + cb + threadIdx.x];
        t[threadIdx.y + i * 8][threadIdx.x] = v;
    }
    __syncthreads();
    #pragma unroll
    for (int i = 0; i < 4; i++) {
        int cc = cb + threadIdx.y + i * 8;
        int k = kb + threadIdx.x;
        if (cc < C && k < Rpad) {
            __nv_bfloat16 h, l;
            split2(t[threadIdx.x][threadIdx.y + i * 8], h, l);
            hi[(size_t)cc * Rpad + k] = h;
            lo[(size_t)cc * Rpad + k] = l;
        }
    }
}

// Gather brand rows + split + pad to NASPAD
__global__ void __launch_bounds__(256)
gather_split(const float* __restrict__ emb, const int* __restrict__ idx,
             __nv_bfloat16* __restrict__ hi, __nv_bfloat16* __restrict__ lo)
{
    const int b = blockIdx.x;
    int row = idx[b];
    row = row < 0 ? 0 : (row >= NBRANDS ? NBRANDS - 1 : row);
    const float4* src = (const float4*)(emb + (size_t)row * NASPECT);
    for (int j = threadIdx.x; j < NASPAD / 4; j += 256) {
        uint2 ph, pl;
        if (j < NASPECT / 4) {
            float4 v = src[j];
            __nv_bfloat16 h[4], l[4];
            split2(v.x, h[0], l[0]); split2(v.y, h[1], l[1]);
            split2(v.z, h[2], l[2]); split2(v.w, h[3], l[3]);
            ph = make_uint2(pack_bf16(h[0], h[1]), pack_bf16(h[2], h[3]));
            pl = make_uint2(pack_bf16(l[0], l[1]), pack_bf16(l[2], l[3]));
        } else {
            ph = make_uint2(0, 0); pl = make_uint2(0, 0);
        }
        ((uint2*)(hi + (size_t)b * NASPAD))[j] = ph;
        ((uint2*)(lo + (size_t)b * NASPAD))[j] = pl;
    }
}

// out[b] = dot(g_F[b,:], g_V[b,:]) / NASPECT
__global__ void __launch_bounds__(256)
final_dot(float* __restrict__ out)
{
    const int b = blockIdx.x;
    const float* f = g_F + (size_t)b * EMBED;
    const float* v = g_V + (size_t)b * EMBED;
    float s = 0.f;
    for (int i = threadIdx.x; i < EMBED; i += 256)
        s = fmaf(f[i], v[i], s);
    #pragma unroll
    for (int off = 16; off > 0; off >>= 1)
        s += __shfl_xor_sync(0xFFFFFFFFu, s, off);
    __shared__ float red[8];
    if ((threadIdx.x & 31) == 0) red[threadIdx.x >> 5] = s;
    __syncthreads();
    if (threadIdx.x < 8) {
        s = red[threadIdx.x];
        #pragma unroll
        for (int off = 4; off > 0; off >>= 1)
            s += __shfl_xor_sync(0xFFu, s, off);
        if (threadIdx.x == 0) out[b] = s * (1.0f / (float)NASPECT);
    }
}

// ---------------------------------------------------------------------------
// Smem sizes: stage = (2*BM + 2*BN) * (BK+8) * 2 bytes; double-buffered.
#define SM_G1 (2 * (2 * 128 + 2 * 128) * (64 + 8) * 2)   // 147456
#define SM_G2 (2 * (2 * 64 + 2 * 64) * (64 + 8) * 2)     // 73728

extern "C" void kernel_launch(void* const* d_in, const int* in_sizes, int n_in,
                              void* d_out, int out_size)
{
    const float* image     = (const float*)d_in[0];
    const int*   brand     = (const int*)d_in[1];
    const float* W1        = (const float*)d_in[2];
    const float* b1        = (const float*)d_in[3];
    const float* W2        = (const float*)d_in[4];
    const float* b2        = (const float*)d_in[5];
    const float* brand_emb = (const float*)d_in[6];
    const float* aspects   = (const float*)d_in[7];
    float*       out       = (float*)d_out;

    static bool init = false;
    static __nv_bfloat16 *pImgH, *pImgL, *pW1TH, *pW1TL, *pHH, *pHL,
                         *pW2TH, *pW2TL, *pGH, *pGL, *pATH, *pATL;
    static float *pF, *pV;
    if (!init) {
        cudaGetSymbolAddress((void**)&pImgH, g_imgH);
        cudaGetSymbolAddress((void**)&pImgL, g_imgL);
        cudaGetSymbolAddress((void**)&pW1TH, g_W1TH);
        cudaGetSymbolAddress((void**)&pW1TL, g_W1TL);
        cudaGetSymbolAddress((void**)&pHH,   g_HH);
        cudaGetSymbolAddress((void**)&pHL,   g_HL);
        cudaGetSymbolAddress((void**)&pW2TH, g_W2TH);
        cudaGetSymbolAddress((void**)&pW2TL, g_W2TL);
        cudaGetSymbolAddress((void**)&pGH,   g_GH);
        cudaGetSymbolAddress((void**)&pGL,   g_GL);
        cudaGetSymbolAddress((void**)&pATH,  g_ATH);
        cudaGetSymbolAddress((void**)&pATL,  g_ATL);
        cudaGetSymbolAddress((void**)&pF,    g_F);
        cudaGetSymbolAddress((void**)&pV,    g_V);
        cudaFuncSetAttribute((const void*)gemm_mma<128,128,64,64,32,0>,
                             cudaFuncAttributeMaxDynamicSharedMemorySize, SM_G1);
        cudaFuncSetAttribute((const void*)gemm_mma<64,64,64,32,16,2>,
                             cudaFuncAttributeMaxDynamicSharedMemorySize, SM_G2);
        cudaFuncSetAttribute((const void*)gemm_mma<64,64,64,32,16,1>,
                             cudaFuncAttributeMaxDynamicSharedMemorySize, SM_G2);
        init = true;
    }

    // Operand conversions
    split_kernel<<<(BATCH * FCIN / 4 + 255) / 256, 256>>>(image, pImgH, pImgL, BATCH * FCIN / 4);
    transpose_split<<<dim3(FCIN / 32, FCIN / 32), dim3(32, 8)>>>(W1, FCIN, FCIN, FCIN, pW1TH, pW1TL);
    transpose_split<<<dim3(FCIN / 32, EMBED / 32), dim3(32, 8)>>>(W2, FCIN, EMBED, FCIN, pW2TH, pW2TL);
    gather_split<<<BATCH, 256>>>(brand_emb, brand, pGH, pGL);
    transpose_split<<<dim3(NASPAD / 32, EMBED / 32), dim3(32, 8)>>>(aspects, NASPECT, EMBED, NASPAD, pATH, pATL);

    // GEMM1: H = lrelu(image @ W1 + b1)  [512,4096] -> bf16 hi/lo
    gemm_mma<128,128,64,64,32,0><<<dim3(FCIN / 128, BATCH / 128), 256, SM_G1>>>(
        pImgH, pImgL, pW1TH, pW1TL, b1, FCIN, FCIN, nullptr, pHH, pHL);

    // GEMM3: V = gather(brand_emb) @ aspects  [512,1024] fp32
    gemm_mma<64,64,64,32,16,2><<<dim3(EMBED / 64, BATCH / 64), 256, SM_G2>>>(
        pGH, pGL, pATH, pATL, nullptr, NASPAD, EMBED, pV, nullptr, nullptr);

    // GEMM2: F = H @ W2 + b2  [512,1024] fp32
    gemm_mma<64,64,64,32,16,1><<<dim3(EMBED / 64, BATCH / 64), 256, SM_G2>>>(
        pHH, pHL, pW2TH, pW2TL, b2, FCIN, EMBED, pF, nullptr, nullptr);

    final_dot<<<BATCH, 256>>>(out);
}

// round 7
// speedup vs baseline: 3.0967x; 1.0329x over previous
#include <cuda_runtime.h>
#include <cuda_bf16.h>
#include <cstdint>

#define BATCH   512
#define FCIN    4096
#define EMBED   1024
#define NASPECT 2000
#define NASPAD  2048
#define NBRANDS 10000

// ---------------------------------------------------------------------------
// Scratch (__device__ globals; no cudaMalloc allowed)
// A-side operands: [M,K] bf16 hi/lo. B-side operands: [K,N] bf16 hi/lo.
// ---------------------------------------------------------------------------
__device__ __align__(256) __nv_bfloat16 g_imgH[BATCH * FCIN];
__device__ __align__(256) __nv_bfloat16 g_imgL[BATCH * FCIN];
__device__ __align__(256) __nv_bfloat16 g_W1H[FCIN * FCIN];     // [K,N]
__device__ __align__(256) __nv_bfloat16 g_W1L[FCIN * FCIN];
__device__ __align__(256) __nv_bfloat16 g_HH[BATCH * FCIN];
__device__ __align__(256) __nv_bfloat16 g_HL[BATCH * FCIN];
__device__ __align__(256) __nv_bfloat16 g_W2H[FCIN * EMBED];    // [K,N]
__device__ __align__(256) __nv_bfloat16 g_W2L[FCIN * EMBED];
__device__ __align__(256) __nv_bfloat16 g_GH[BATCH * NASPAD];
__device__ __align__(256) __nv_bfloat16 g_GL[BATCH * NASPAD];
__device__ __align__(256) __nv_bfloat16 g_ASH[NASPAD * EMBED];  // [Kpad,N]
__device__ __align__(256) __nv_bfloat16 g_ASL[NASPAD * EMBED];
__device__ __align__(256) float g_F[BATCH * EMBED];
__device__ __align__(256) float g_V[BATCH * EMBED];

// ---------------------------------------------------------------------------
// sm_80-era PTX helpers
// ---------------------------------------------------------------------------
__device__ __forceinline__ uint32_t smem_u32(const void* p) {
    uint32_t a;
    asm("{ .reg .u64 t; cvta.to.shared.u64 t, %1; cvt.u32.u64 %0, t; }"
        : "=r"(a) : "l"(p));
    return a;
}
__device__ __forceinline__ void ldsm4(uint32_t* r, uint32_t addr) {
    asm volatile("ldmatrix.sync.aligned.m8n8.x4.shared.b16 {%0,%1,%2,%3}, [%4];"
        : "=r"(r[0]), "=r"(r[1]), "=r"(r[2]), "=r"(r[3]) : "r"(addr));
}
__device__ __forceinline__ void ldsm2t(uint32_t* r, uint32_t addr) {
    asm volatile("ldmatrix.sync.aligned.m8n8.x2.trans.shared.b16 {%0,%1}, [%2];"
        : "=r"(r[0]), "=r"(r[1]) : "r"(addr));
}
__device__ __forceinline__ void mma_bf16(float* d, const uint32_t* a, const uint32_t* b) {
    asm volatile("mma.sync.aligned.m16n8k16.row.col.f32.bf16.bf16.f32 "
        "{%0,%1,%2,%3}, {%4,%5,%6,%7}, {%8,%9}, {%0,%1,%2,%3};"
        : "+f"(d[0]), "+f"(d[1]), "+f"(d[2]), "+f"(d[3])
        : "r"(a[0]), "r"(a[1]), "r"(a[2]), "r"(a[3]), "r"(b[0]), "r"(b[1]));
}
__device__ __forceinline__ void cpa16(uint32_t d, const void* s) {
    asm volatile("cp.async.cg.shared.global [%0], [%1], 16;" :: "r"(d), "l"(s));
}
#define CPA_COMMIT() asm volatile("cp.async.commit_group;" ::: "memory")
#define CPA_WAIT(n)  asm volatile("cp.async.wait_group %0;" :: "n"(n) : "memory")

__device__ __forceinline__ void split2(float x, __nv_bfloat16& h, __nv_bfloat16& l) {
    h = __float2bfloat16(x);
    l = __float2bfloat16(x - __bfloat162float(h));
}
__device__ __forceinline__ uint32_t pack_bf16(__nv_bfloat16 a, __nv_bfloat16 b) {
    return (uint32_t)*(uint16_t*)&a | ((uint32_t)*(uint16_t*)&b << 16);
}

// ---------------------------------------------------------------------------
// bf16 3-MMA split GEMM on mma.sync (m16n8k16):
//   C = Ah·Bh + Ah·Bl + Al·Bh
// A: [M,K] row-major bf16 hi/lo. B: [K,N] row-major bf16 hi/lo (natural layout;
// fragments produced with ldmatrix.trans). 8 warps (BM/WM x BN/WN), BK=64,
// cp.async double-buffered. Row pads: A tile +8 elems, B tile +8 elems
// (stride == 16 mod 128 bytes -> conflict-free ldmatrix).
// EPI: 0 = +bias, lrelu, write bf16 hi/lo; 1 = +bias fp32; 2 = fp32.
// ---------------------------------------------------------------------------
template<int BM, int BN, int BK, int WM, int WN, int EPI>
__global__ void __launch_bounds__(256)
gemm_mma(const __nv_bfloat16* __restrict__ Ah, const __nv_bfloat16* __restrict__ Al,
         const __nv_bfloat16* __restrict__ Bh, const __nv_bfloat16* __restrict__ Bl,
         const float* __restrict__ bias, int K, int ldb, int ldc,
         float* __restrict__ Cf, __nv_bfloat16* __restrict__ Ch,
         __nv_bfloat16* __restrict__ Cl)
{
    constexpr int SA = (BK + 8) * 2;               // A smem row bytes
    constexpr int SB = (BN + 8) * 2;               // B smem row bytes
    constexpr int OFF_AH = 0;
    constexpr int OFF_AL = BM * SA;
    constexpr int OFF_BH = 2 * BM * SA;
    constexpr int OFF_BL = 2 * BM * SA + BK * SB;
    constexpr int BUFB = 2 * BM * SA + 2 * BK * SB;
    constexpr int MI = WM / 16, NI = WN / 8;
    constexpr int KS = BK / 16;
    constexpr int AK8 = BK / 8;                    // 16B chunks per A row
    constexpr int BN8 = BN / 8;                    // 16B chunks per B row

    extern __shared__ __align__(128) char smem[];
    const uint32_t sb = smem_u32(smem);
    const int tid = threadIdx.x, wid = tid >> 5, lane = tid & 31;
    const int wm = wid % (BM / WM), wn = wid / (BM / WM);
    const int rowbase = blockIdx.y * BM, colbase = blockIdx.x * BN;

    const __nv_bfloat16* srcA[2] = { Ah + (size_t)rowbase * K, Al + (size_t)rowbase * K };
    const __nv_bfloat16* srcB[2] = { Bh + colbase, Bl + colbase };

    float acc[MI][NI][4];
    #pragma unroll
    for (int i = 0; i < MI; i++)
        #pragma unroll
        for (int j = 0; j < NI; j++)
            #pragma unroll
            for (int q = 0; q < 4; q++) acc[i][j][q] = 0.f;

    // ldmatrix per-thread base byte offsets
    const uint32_t aBase = (uint32_t)((wm * WM + (lane & 15)) * SA + (lane >> 4) * 16);
    const uint32_t bBase = (uint32_t)((lane & 15) * SB + (wn * WN) * 2);

    auto prefetch = [&](int chunk, int p) {
        const uint32_t tb = sb + p * BUFB;
        const int k0 = chunk * BK;
        #pragma unroll
        for (int i = tid; i < BM * AK8; i += 256) {        // A hi + lo
            int r = i / AK8, c = i % AK8;
            uint32_t d = (uint32_t)(r * SA + c * 16);
            cpa16(tb + OFF_AH + d, srcA[0] + (size_t)r * K + k0 + c * 8);
            cpa16(tb + OFF_AL + d, srcA[1] + (size_t)r * K + k0 + c * 8);
        }
        #pragma unroll
        for (int i = tid; i < BK * BN8; i += 256) {        // B hi + lo ([K,N])
            int r = i / BN8, c = i % BN8;
            uint32_t d = (uint32_t)(r * SB + c * 16);
            cpa16(tb + OFF_BH + d, srcB[0] + (size_t)(k0 + r) * ldb + c * 8);
            cpa16(tb + OFF_BL + d, srcB[1] + (size_t)(k0 + r) * ldb + c * 8);
        }
        CPA_COMMIT();
    };

    const int NC = K / BK;
    prefetch(0, 0);

    for (int c = 0; c < NC; c++) {
        const int p = c & 1;
        if (c + 1 < NC) { prefetch(c + 1, (c + 1) & 1); CPA_WAIT(1); }
        else            { CPA_WAIT(0); }
        __syncthreads();

        const uint32_t tb = sb + p * BUFB;
        #pragma unroll
        for (int ks = 0; ks < KS; ks++) {
            uint32_t aH[MI][4], aL[MI][4], bH[NI][2], bL[NI][2];
            #pragma unroll
            for (int mi = 0; mi < MI; mi++) {
                uint32_t o = aBase + (uint32_t)(mi * 16 * SA + ks * 32);
                ldsm4(aH[mi], tb + OFF_AH + o);
                ldsm4(aL[mi], tb + OFF_AL + o);
            }
            #pragma unroll
            for (int ni = 0; ni < NI; ni++) {
                uint32_t o = bBase + (uint32_t)(ks * 16 * SB + ni * 16);
                ldsm2t(bH[ni], tb + OFF_BH + o);
                ldsm2t(bL[ni], tb + OFF_BL + o);
            }
            #pragma unroll
            for (int mi = 0; mi < MI; mi++)
                #pragma unroll
                for (int ni = 0; ni < NI; ni++) {
                    mma_bf16(acc[mi][ni], aH[mi], bH[ni]);
                    mma_bf16(acc[mi][ni], aH[mi], bL[ni]);
                    mma_bf16(acc[mi][ni], aL[mi], bH[ni]);
                }
        }
        __syncthreads();
    }

    // Epilogue. Fragment map: d0,d1 -> row lane>>2, cols (lane&3)*2,+1; d2,d3 -> +8 rows.
    const int r0 = rowbase + wm * WM + (lane >> 2);
    const int c0 = colbase + wn * WN + (lane & 3) * 2;
    #pragma unroll
    for (int mi = 0; mi < MI; mi++) {
        #pragma unroll
        for (int ni = 0; ni < NI; ni++) {
            const int cc = c0 + ni * 8;
            float b0 = 0.f, b1 = 0.f;
            if (EPI == 0 || EPI == 1) { b0 = __ldg(&bias[cc]); b1 = __ldg(&bias[cc + 1]); }
            #pragma unroll
            for (int h = 0; h < 2; h++) {
                const int rr = r0 + mi * 16 + h * 8;
                float v0 = acc[mi][ni][2 * h]     + b0;
                float v1 = acc[mi][ni][2 * h + 1] + b1;
                if (EPI == 0) {
                    v0 = v0 > 0.f ? v0 : 0.01f * v0;
                    v1 = v1 > 0.f ? v1 : 0.01f * v1;
                    __nv_bfloat16 h0, l0, h1, l1;
                    split2(v0, h0, l0); split2(v1, h1, l1);
                    *(uint32_t*)(Ch + (size_t)rr * ldc + cc) = pack_bf16(h0, h1);
                    *(uint32_t*)(Cl + (size_t)rr * ldc + cc) = pack_bf16(l0, l1);
                } else {
                    *(float2*)(Cf + (size_t)rr * ldc + cc) = make_float2(v0, v1);
                }
            }
        }
    }
}

// ---------------------------------------------------------------------------
// Elementwise split with optional zero suffix: out [total4*4] elems; indices
// >= valid4*4 write zero. Fully coalesced (uint2 per thread per array).
// ---------------------------------------------------------------------------
__global__ void __launch_bounds__(256)
split_pad(const float* __restrict__ in, __nv_bfloat16* __restrict__ hi,
          __nv_bfloat16* __restrict__ lo, int total4, int valid4)
{
    int i = blockIdx.x * 256 + threadIdx.x;
    if (i >= total4) return;
    uint2 ph = make_uint2(0, 0), pl = make_uint2(0, 0);
    if (i < valid4) {
        float4 v = ((const float4*)in)[i];
        __nv_bfloat16 h[4], l[4];
        split2(v.x, h[0], l[0]); split2(v.y, h[1], l[1]);
        split2(v.z, h[2], l[2]); split2(v.w, h[3], l[3]);
        ph = make_uint2(pack_bf16(h[0], h[1]), pack_bf16(h[2], h[3]));
        pl = make_uint2(pack_bf16(l[0], l[1]), pack_bf16(l[2], l[3]));
    }
    ((uint2*)hi)[i] = ph;
    ((uint2*)lo)[i] = pl;
}

// Gather brand rows + split + pad to NASPAD
__global__ void __launch_bounds__(256)
gather_split(const float* __restrict__ emb, const int* __restrict__ idx,
             __nv_bfloat16* __restrict__ hi, __nv_bfloat16* __restrict__ lo)
{
    const int b = blockIdx.x;
    int row = idx[b];
    row = row < 0 ? 0 : (row >= NBRANDS ? NBRANDS - 1 : row);
    const float4* src = (const float4*)(emb + (size_t)row * NASPECT);
    for (int j = threadIdx.x; j < NASPAD / 4; j += 256) {
        uint2 ph = make_uint2(0, 0), pl = make_uint2(0, 0);
        if (j < NASPECT / 4) {
            float4 v = src[j];
            __nv_bfloat16 h[4], l[4];
            split2(v.x, h[0], l[0]); split2(v.y, h[1], l[1]);
            split2(v.z, h[2], l[2]); split2(v.w, h[3], l[3]);
            ph = make_uint2(pack_bf16(h[0], h[1]), pack_bf16(h[2], h[3]));
            pl = make_uint2(pack_bf16(l[0], l[1]), pack_bf16(l[2], l[3]));
        }
        ((uint2*)(hi + (size_t)b * NASPAD))[j] = ph;
        ((uint2*)(lo + (size_t)b * NASPAD))[j] = pl;
    }
}

// out[b] = dot(g_F[b,:], g_V[b,:]) / NASPECT
__global__ void __launch_bounds__(256)
final_dot(float* __restrict__ out)
{
    const int b = blockIdx.x;
    const float* f = g_F + (size_t)b * EMBED;
    const float* v = g_V + (size_t)b * EMBED;
    float s = 0.f;
    for (int i = threadIdx.x; i < EMBED; i += 256)
        s = fmaf(f[i], v[i], s);
    #pragma unroll
    for (int off = 16; off > 0; off >>= 1)
        s += __shfl_xor_sync(0xFFFFFFFFu, s, off);
    __shared__ float red[8];
    if ((threadIdx.x & 31) == 0) red[threadIdx.x >> 5] = s;
    __syncthreads();
    if (threadIdx.x < 8) {
        s = red[threadIdx.x];
        #pragma unroll
        for (int off = 4; off > 0; off >>= 1)
            s += __shfl_xor_sync(0xFFu, s, off);
        if (threadIdx.x == 0) out[b] = s * (1.0f / (float)NASPECT);
    }
}

// ---------------------------------------------------------------------------
// Smem per stage: 2*BM*(BK+8)*2 + 2*BK*(BN+8)*2 ; double-buffered.
#define SM_G1 (2 * (2 * 128 * (64 + 8) * 2 + 2 * 64 * (128 + 8) * 2))  // 143360
#define SM_G2 (2 * (2 * 64 * (64 + 8) * 2 + 2 * 64 * (64 + 8) * 2))    // 73728

extern "C" void kernel_launch(void* const* d_in, const int* in_sizes, int n_in,
                              void* d_out, int out_size)
{
    const float* image     = (const float*)d_in[0];
    const int*   brand     = (const int*)d_in[1];
    const float* W1        = (const float*)d_in[2];
    const float* b1        = (const float*)d_in[3];
    const float* W2        = (const float*)d_in[4];
    const float* b2        = (const float*)d_in[5];
    const float* brand_emb = (const float*)d_in[6];
    const float* aspects   = (const float*)d_in[7];
    float*       out       = (float*)d_out;

    static bool init = false;
    static __nv_bfloat16 *pImgH, *pImgL, *pW1H, *pW1L, *pHH, *pHL,
                         *pW2H, *pW2L, *pGH, *pGL, *pASH, *pASL;
    static float *pF, *pV;
    if (!init) {
        cudaGetSymbolAddress((void**)&pImgH, g_imgH);
        cudaGetSymbolAddress((void**)&pImgL, g_imgL);
        cudaGetSymbolAddress((void**)&pW1H,  g_W1H);
        cudaGetSymbolAddress((void**)&pW1L,  g_W1L);
        cudaGetSymbolAddress((void**)&pHH,   g_HH);
        cudaGetSymbolAddress((void**)&pHL,   g_HL);
        cudaGetSymbolAddress((void**)&pW2H,  g_W2H);
        cudaGetSymbolAddress((void**)&pW2L,  g_W2L);
        cudaGetSymbolAddress((void**)&pGH,   g_GH);
        cudaGetSymbolAddress((void**)&pGL,   g_GL);
        cudaGetSymbolAddress((void**)&pASH,  g_ASH);
        cudaGetSymbolAddress((void**)&pASL,  g_ASL);
        cudaGetSymbolAddress((void**)&pF,    g_F);
        cudaGetSymbolAddress((void**)&pV,    g_V);
        cudaFuncSetAttribute((const void*)gemm_mma<128,128,64,64,32,0>,
                             cudaFuncAttributeMaxDynamicSharedMemorySize, SM_G1);
        cudaFuncSetAttribute((const void*)gemm_mma<64,64,64,32,16,2>,
                             cudaFuncAttributeMaxDynamicSharedMemorySize, SM_G2);
        cudaFuncSetAttribute((const void*)gemm_mma<64,64,64,32,16,1>,
                             cudaFuncAttributeMaxDynamicSharedMemorySize, SM_G2);
        init = true;
    }

    // Operand conversions (all coalesced elementwise; no transposes)
    split_pad<<<(BATCH * FCIN / 4 + 255) / 256, 256>>>(
        image, pImgH, pImgL, BATCH * FCIN / 4, BATCH * FCIN / 4);
    split_pad<<<(FCIN * FCIN / 4 + 255) / 256, 256>>>(
        W1, pW1H, pW1L, FCIN * FCIN / 4, FCIN * FCIN / 4);
    split_pad<<<(FCIN * EMBED / 4 + 255) / 256, 256>>>(
        W2, pW2H, pW2L, FCIN * EMBED / 4, FCIN * EMBED / 4);
    split_pad<<<(NASPAD * EMBED / 4 + 255) / 256, 256>>>(
        aspects, pASH, pASL, NASPAD * EMBED / 4, NASPECT * EMBED / 4);
    gather_split<<<BATCH, 256>>>(brand_emb, brand, pGH, pGL);

    // GEMM1: H = lrelu(image @ W1 + b1)  [512,4096] -> bf16 hi/lo
    gemm_mma<128,128,64,64,32,0><<<dim3(FCIN / 128, BATCH / 128), 256, SM_G1>>>(
        pImgH, pImgL, pW1H, pW1L, b1, FCIN, FCIN, FCIN, nullptr, pHH, pHL);

    // GEMM3: V = gather(brand_emb) @ aspects  [512,1024] fp32
    gemm_mma<64,64,64,32,16,2><<<dim3(EMBED / 64, BATCH / 64), 256, SM_G2>>>(
        pGH, pGL, pASH, pASL, nullptr, NASPAD, EMBED, EMBED, pV, nullptr, nullptr);

    // GEMM2: F = H @ W2 + b2  [512,1024] fp32
    gemm_mma<64,64,64,32,16,1><<<dim3(EMBED / 64, BATCH / 64), 256, SM_G2>>>(
        pHH, pHL, pW2H, pW2L, b2, FCIN, EMBED, EMBED, pF, nullptr, nullptr);

    final_dot<<<BATCH, 256>>>(out);
}

// round 8
// speedup vs baseline: 3.7499x; 1.2109x over previous
#include <cuda_runtime.h>
#include <cuda_bf16.h>
#include <cuda_fp16.h>
#include <cstdint>

#define BATCH   512
#define FCIN    4096
#define EMBED   1024
#define NASPECT 2000
#define NASPAD  2048
#define NBRANDS 10000

// ---------------------------------------------------------------------------
// Scratch (__device__ globals)
// GEMM1: A = fp16(image) single, B = W1 fp16 hi/lo  -> H bf16 hi/lo
// GEMM2/3: bf16 3-MMA split (unchanged from R7)
// ---------------------------------------------------------------------------
__device__ __align__(256) __half         g_imgF[BATCH * FCIN];
__device__ __align__(256) __half         g_W1H[FCIN * FCIN];     // [K,N]
__device__ __align__(256) __half         g_W1L[FCIN * FCIN];
__device__ __align__(256) __nv_bfloat16 g_HH[BATCH * FCIN];
__device__ __align__(256) __nv_bfloat16 g_HL[BATCH * FCIN];
__device__ __align__(256) __nv_bfloat16 g_W2H[FCIN * EMBED];    // [K,N]
__device__ __align__(256) __nv_bfloat16 g_W2L[FCIN * EMBED];
__device__ __align__(256) __nv_bfloat16 g_GH[BATCH * NASPAD];
__device__ __align__(256) __nv_bfloat16 g_GL[BATCH * NASPAD];
__device__ __align__(256) __nv_bfloat16 g_ASH[NASPAD * EMBED];  // [Kpad,N]
__device__ __align__(256) __nv_bfloat16 g_ASL[NASPAD * EMBED];
__device__ __align__(256) float g_F[BATCH * EMBED];
__device__ __align__(256) float g_V[BATCH * EMBED];

// ---------------------------------------------------------------------------
// PTX helpers
// ---------------------------------------------------------------------------
__device__ __forceinline__ uint32_t smem_u32(const void* p) {
    uint32_t a;
    asm("{ .reg .u64 t; cvta.to.shared.u64 t, %1; cvt.u32.u64 %0, t; }"
        : "=r"(a) : "l"(p));
    return a;
}
__device__ __forceinline__ void ldsm4(uint32_t* r, uint32_t addr) {
    asm volatile("ldmatrix.sync.aligned.m8n8.x4.shared.b16 {%0,%1,%2,%3}, [%4];"
        : "=r"(r[0]), "=r"(r[1]), "=r"(r[2]), "=r"(r[3]) : "r"(addr));
}
__device__ __forceinline__ void ldsm2t(uint32_t* r, uint32_t addr) {
    asm volatile("ldmatrix.sync.aligned.m8n8.x2.trans.shared.b16 {%0,%1}, [%2];"
        : "=r"(r[0]), "=r"(r[1]) : "r"(addr));
}
__device__ __forceinline__ void mma_bf16(float* d, const uint32_t* a, const uint32_t* b) {
    asm volatile("mma.sync.aligned.m16n8k16.row.col.f32.bf16.bf16.f32 "
        "{%0,%1,%2,%3}, {%4,%5,%6,%7}, {%8,%9}, {%0,%1,%2,%3};"
        : "+f"(d[0]), "+f"(d[1]), "+f"(d[2]), "+f"(d[3])
        : "r"(a[0]), "r"(a[1]), "r"(a[2]), "r"(a[3]), "r"(b[0]), "r"(b[1]));
}
__device__ __forceinline__ void mma_f16(float* d, const uint32_t* a, const uint32_t* b) {
    asm volatile("mma.sync.aligned.m16n8k16.row.col.f32.f16.f16.f32 "
        "{%0,%1,%2,%3}, {%4,%5,%6,%7}, {%8,%9}, {%0,%1,%2,%3};"
        : "+f"(d[0]), "+f"(d[1]), "+f"(d[2]), "+f"(d[3])
        : "r"(a[0]), "r"(a[1]), "r"(a[2]), "r"(a[3]), "r"(b[0]), "r"(b[1]));
}
__device__ __forceinline__ void cpa16(uint32_t d, const void* s) {
    asm volatile("cp.async.cg.shared.global [%0], [%1], 16;" :: "r"(d), "l"(s));
}
#define CPA_COMMIT() asm volatile("cp.async.commit_group;" ::: "memory")
#define CPA_WAIT(n)  asm volatile("cp.async.wait_group %0;" :: "n"(n) : "memory")

__device__ __forceinline__ void split2(float x, __nv_bfloat16& h, __nv_bfloat16& l) {
    h = __float2bfloat16(x);
    l = __float2bfloat16(x - __bfloat162float(h));
}
__device__ __forceinline__ void split2h(float x, __half& h, __half& l) {
    h = __float2half_rn(x);
    l = __float2half_rn(x - __half2float(h));
}
__device__ __forceinline__ uint32_t pack_bf16(__nv_bfloat16 a, __nv_bfloat16 b) {
    return (uint32_t)*(uint16_t*)&a | ((uint32_t)*(uint16_t*)&b << 16);
}
__device__ __forceinline__ uint32_t pack_f16(__half a, __half b) {
    return (uint32_t)*(uint16_t*)&a | ((uint32_t)*(uint16_t*)&b << 16);
}

// ---------------------------------------------------------------------------
// GEMM1 core: fp16 2-MMA:  C = A·Bh + A·Bl
// A: [M,K] fp16 (single). B: [K,N] fp16 hi/lo. Epilogue: +bias, lrelu,
// write bf16 hi/lo H. 8 warps (BM/WM x BN/WN), BK=64, cp.async double-buffered.
// ---------------------------------------------------------------------------
template<int BM, int BN, int BK, int WM, int WN>
__global__ void __launch_bounds__(256)
gemm_f16x2(const __half* __restrict__ A,
           const __half* __restrict__ Bh, const __half* __restrict__ Bl,
           const float* __restrict__ bias, int K, int ldb, int ldc,
           __nv_bfloat16* __restrict__ Ch, __nv_bfloat16* __restrict__ Cl)
{
    constexpr int SA = (BK + 8) * 2;
    constexpr int SB = (BN + 8) * 2;
    constexpr int OFF_A  = 0;
    constexpr int OFF_BH = BM * SA;
    constexpr int OFF_BL = BM * SA + BK * SB;
    constexpr int BUFB = BM * SA + 2 * BK * SB;
    constexpr int MI = WM / 16, NI = WN / 8;
    constexpr int KS = BK / 16;
    constexpr int AK8 = BK / 8;
    constexpr int BN8 = BN / 8;

    extern __shared__ __align__(128) char smem[];
    const uint32_t sb = smem_u32(smem);
    const int tid = threadIdx.x, wid = tid >> 5, lane = tid & 31;
    const int wm = wid % (BM / WM), wn = wid / (BM / WM);
    const int rowbase = blockIdx.y * BM, colbase = blockIdx.x * BN;

    const __half* srcA = A + (size_t)rowbase * K;
    const __half* srcB[2] = { Bh + colbase, Bl + colbase };

    float acc[MI][NI][4];
    #pragma unroll
    for (int i = 0; i < MI; i++)
        #pragma unroll
        for (int j = 0; j < NI; j++)
            #pragma unroll
            for (int q = 0; q < 4; q++) acc[i][j][q] = 0.f;

    const uint32_t aBase = (uint32_t)((wm * WM + (lane & 15)) * SA + (lane >> 4) * 16);
    const uint32_t bBase = (uint32_t)((lane & 15) * SB + (wn * WN) * 2);

    auto prefetch = [&](int chunk, int p) {
        const uint32_t tb = sb + p * BUFB;
        const int k0 = chunk * BK;
        #pragma unroll
        for (int i = tid; i < BM * AK8; i += 256) {
            int r = i / AK8, c = i % AK8;
            cpa16(tb + OFF_A + (uint32_t)(r * SA + c * 16),
                  srcA + (size_t)r * K + k0 + c * 8);
        }
        #pragma unroll
        for (int i = tid; i < BK * BN8; i += 256) {
            int r = i / BN8, c = i % BN8;
            uint32_t d = (uint32_t)(r * SB + c * 16);
            cpa16(tb + OFF_BH + d, srcB[0] + (size_t)(k0 + r) * ldb + c * 8);
            cpa16(tb + OFF_BL + d, srcB[1] + (size_t)(k0 + r) * ldb + c * 8);
        }
        CPA_COMMIT();
    };

    const int NC = K / BK;
    prefetch(0, 0);

    for (int c = 0; c < NC; c++) {
        const int p = c & 1;
        if (c + 1 < NC) { prefetch(c + 1, (c + 1) & 1); CPA_WAIT(1); }
        else            { CPA_WAIT(0); }
        __syncthreads();

        const uint32_t tb = sb + p * BUFB;
        #pragma unroll
        for (int ks = 0; ks < KS; ks++) {
            uint32_t aF[MI][4], bH[NI][2], bL[NI][2];
            #pragma unroll
            for (int mi = 0; mi < MI; mi++)
                ldsm4(aF[mi], tb + OFF_A + aBase + (uint32_t)(mi * 16 * SA + ks * 32));
            #pragma unroll
            for (int ni = 0; ni < NI; ni++) {
                uint32_t o = bBase + (uint32_t)(ks * 16 * SB + ni * 16);
                ldsm2t(bH[ni], tb + OFF_BH + o);
                ldsm2t(bL[ni], tb + OFF_BL + o);
            }
            #pragma unroll
            for (int mi = 0; mi < MI; mi++)
                #pragma unroll
                for (int ni = 0; ni < NI; ni++) {
                    mma_f16(acc[mi][ni], aF[mi], bH[ni]);
                    mma_f16(acc[mi][ni], aF[mi], bL[ni]);
                }
        }
        __syncthreads();
    }

    const int r0 = rowbase + wm * WM + (lane >> 2);
    const int c0 = colbase + wn * WN + (lane & 3) * 2;
    #pragma unroll
    for (int mi = 0; mi < MI; mi++) {
        #pragma unroll
        for (int ni = 0; ni < NI; ni++) {
            const int cc = c0 + ni * 8;
            const float b0 = __ldg(&bias[cc]), b1 = __ldg(&bias[cc + 1]);
            #pragma unroll
            for (int h = 0; h < 2; h++) {
                const int rr = r0 + mi * 16 + h * 8;
                float v0 = acc[mi][ni][2 * h]     + b0;
                float v1 = acc[mi][ni][2 * h + 1] + b1;
                v0 = v0 > 0.f ? v0 : 0.01f * v0;
                v1 = v1 > 0.f ? v1 : 0.01f * v1;
                __nv_bfloat16 h0, l0, h1, l1;
                split2(v0, h0, l0); split2(v1, h1, l1);
                *(uint32_t*)(Ch + (size_t)rr * ldc + cc) = pack_bf16(h0, h1);
                *(uint32_t*)(Cl + (size_t)rr * ldc + cc) = pack_bf16(l0, l1);
            }
        }
    }
}

// ---------------------------------------------------------------------------
// bf16 3-MMA split GEMM (unchanged R7 core). EPI: 1 = +bias fp32; 2 = fp32.
// ---------------------------------------------------------------------------
template<int BM, int BN, int BK, int WM, int WN, int EPI>
__global__ void __launch_bounds__(256)
gemm_mma(const __nv_bfloat16* __restrict__ Ah, const __nv_bfloat16* __restrict__ Al,
         const __nv_bfloat16* __restrict__ Bh, const __nv_bfloat16* __restrict__ Bl,
         const float* __restrict__ bias, int K, int ldb, int ldc,
         float* __restrict__ Cf)
{
    constexpr int SA = (BK + 8) * 2;
    constexpr int SB = (BN + 8) * 2;
    constexpr int OFF_AH = 0;
    constexpr int OFF_AL = BM * SA;
    constexpr int OFF_BH = 2 * BM * SA;
    constexpr int OFF_BL = 2 * BM * SA + BK * SB;
    constexpr int BUFB = 2 * BM * SA + 2 * BK * SB;
    constexpr int MI = WM / 16, NI = WN / 8;
    constexpr int KS = BK / 16;
    constexpr int AK8 = BK / 8;
    constexpr int BN8 = BN / 8;

    extern __shared__ __align__(128) char smem[];
    const uint32_t sb = smem_u32(smem);
    const int tid = threadIdx.x, wid = tid >> 5, lane = tid & 31;
    const int wm = wid % (BM / WM), wn = wid / (BM / WM);
    const int rowbase = blockIdx.y * BM, colbase = blockIdx.x * BN;

    const __nv_bfloat16* srcA[2] = { Ah + (size_t)rowbase * K, Al + (size_t)rowbase * K };
    const __nv_bfloat16* srcB[2] = { Bh + colbase, Bl + colbase };

    float acc[MI][NI][4];
    #pragma unroll
    for (int i = 0; i < MI; i++)
        #pragma unroll
        for (int j = 0; j < NI; j++)
            #pragma unroll
            for (int q = 0; q < 4; q++) acc[i][j][q] = 0.f;

    const uint32_t aBase = (uint32_t)((wm * WM + (lane & 15)) * SA + (lane >> 4) * 16);
    const uint32_t bBase = (uint32_t)((lane & 15) * SB + (wn * WN) * 2);

    auto prefetch = [&](int chunk, int p) {
        const uint32_t tb = sb + p * BUFB;
        const int k0 = chunk * BK;
        #pragma unroll
        for (int i = tid; i < BM * AK8; i += 256) {
            int r = i / AK8, c = i % AK8;
            uint32_t d = (uint32_t)(r * SA + c * 16);
            cpa16(tb + OFF_AH + d, srcA[0] + (size_t)r * K + k0 + c * 8);
            cpa16(tb + OFF_AL + d, srcA[1] + (size_t)r * K + k0 + c * 8);
        }
        #pragma unroll
        for (int i = tid; i < BK * BN8; i += 256) {
            int r = i / BN8, c = i % BN8;
            uint32_t d = (uint32_t)(r * SB + c * 16);
            cpa16(tb + OFF_BH + d, srcB[0] + (size_t)(k0 + r) * ldb + c * 8);
            cpa16(tb + OFF_BL + d, srcB[1] + (size_t)(k0 + r) * ldb + c * 8);
        }
        CPA_COMMIT();
    };

    const int NC = K / BK;
    prefetch(0, 0);

    for (int c = 0; c < NC; c++) {
        const int p = c & 1;
        if (c + 1 < NC) { prefetch(c + 1, (c + 1) & 1); CPA_WAIT(1); }
        else            { CPA_WAIT(0); }
        __syncthreads();

        const uint32_t tb = sb + p * BUFB;
        #pragma unroll
        for (int ks = 0; ks < KS; ks++) {
            uint32_t aH[MI][4], aL[MI][4], bH[NI][2], bL[NI][2];
            #pragma unroll
            for (int mi = 0; mi < MI; mi++) {
                uint32_t o = aBase + (uint32_t)(mi * 16 * SA + ks * 32);
                ldsm4(aH[mi], tb + OFF_AH + o);
                ldsm4(aL[mi], tb + OFF_AL + o);
            }
            #pragma unroll
            for (int ni = 0; ni < NI; ni++) {
                uint32_t o = bBase + (uint32_t)(ks * 16 * SB + ni * 16);
                ldsm2t(bH[ni], tb + OFF_BH + o);
                ldsm2t(bL[ni], tb + OFF_BL + o);
            }
            #pragma unroll
            for (int mi = 0; mi < MI; mi++)
                #pragma unroll
                for (int ni = 0; ni < NI; ni++) {
                    mma_bf16(acc[mi][ni], aH[mi], bH[ni]);
                    mma_bf16(acc[mi][ni], aH[mi], bL[ni]);
                    mma_bf16(acc[mi][ni], aL[mi], bH[ni]);
                }
        }
        __syncthreads();
    }

    const int r0 = rowbase + wm * WM + (lane >> 2);
    const int c0 = colbase + wn * WN + (lane & 3) * 2;
    #pragma unroll
    for (int mi = 0; mi < MI; mi++) {
        #pragma unroll
        for (int ni = 0; ni < NI; ni++) {
            const int cc = c0 + ni * 8;
            float b0 = 0.f, b1 = 0.f;
            if (EPI == 1) { b0 = __ldg(&bias[cc]); b1 = __ldg(&bias[cc + 1]); }
            #pragma unroll
            for (int h = 0; h < 2; h++) {
                const int rr = r0 + mi * 16 + h * 8;
                *(float2*)(Cf + (size_t)rr * ldc + cc) =
                    make_float2(acc[mi][ni][2 * h] + b0, acc[mi][ni][2 * h + 1] + b1);
            }
        }
    }
}

// ---------------------------------------------------------------------------
// Conversion kernels
// ---------------------------------------------------------------------------
// fp32 -> fp16 cast (single array), vectorized by 4
__global__ void __launch_bounds__(256)
cast_half(const float* __restrict__ in, __half* __restrict__ o, int n4)
{
    int i = blockIdx.x * 256 + threadIdx.x;
    if (i >= n4) return;
    float4 v = ((const float4*)in)[i];
    ((uint2*)o)[i] = make_uint2(pack_f16(__float2half_rn(v.x), __float2half_rn(v.y)),
                                pack_f16(__float2half_rn(v.z), __float2half_rn(v.w)));
}

// fp32 -> fp16 hi/lo split
__global__ void __launch_bounds__(256)
split_half(const float* __restrict__ in, __half* __restrict__ hi,
           __half* __restrict__ lo, int n4)
{
    int i = blockIdx.x * 256 + threadIdx.x;
    if (i >= n4) return;
    float4 v = ((const float4*)in)[i];
    __half h[4], l[4];
    split2h(v.x, h[0], l[0]); split2h(v.y, h[1], l[1]);
    split2h(v.z, h[2], l[2]); split2h(v.w, h[3], l[3]);
    ((uint2*)hi)[i] = make_uint2(pack_f16(h[0], h[1]), pack_f16(h[2], h[3]));
    ((uint2*)lo)[i] = make_uint2(pack_f16(l[0], l[1]), pack_f16(l[2], l[3]));
}

// fp32 -> bf16 hi/lo split with zero suffix
__global__ void __launch_bounds__(256)
split_pad(const float* __restrict__ in, __nv_bfloat16* __restrict__ hi,
          __nv_bfloat16* __restrict__ lo, int total4, int valid4)
{
    int i = blockIdx.x * 256 + threadIdx.x;
    if (i >= total4) return;
    uint2 ph = make_uint2(0, 0), pl = make_uint2(0, 0);
    if (i < valid4) {
        float4 v = ((const float4*)in)[i];
        __nv_bfloat16 h[4], l[4];
        split2(v.x, h[0], l[0]); split2(v.y, h[1], l[1]);
        split2(v.z, h[2], l[2]); split2(v.w, h[3], l[3]);
        ph = make_uint2(pack_bf16(h[0], h[1]), pack_bf16(h[2], h[3]));
        pl = make_uint2(pack_bf16(l[0], l[1]), pack_bf16(l[2], l[3]));
    }
    ((uint2*)hi)[i] = ph;
    ((uint2*)lo)[i] = pl;
}

// Gather brand rows + split + pad to NASPAD (bf16)
__global__ void __launch_bounds__(256)
gather_split(const float* __restrict__ emb, const int* __restrict__ idx,
             __nv_bfloat16* __restrict__ hi, __nv_bfloat16* __restrict__ lo)
{
    const int b = blockIdx.x;
    int row = idx[b];
    row = row < 0 ? 0 : (row >= NBRANDS ? NBRANDS - 1 : row);
    const float4* src = (const float4*)(emb + (size_t)row * NASPECT);
    for (int j = threadIdx.x; j < NASPAD / 4; j += 256) {
        uint2 ph = make_uint2(0, 0), pl = make_uint2(0, 0);
        if (j < NASPECT / 4) {
            float4 v = src[j];
            __nv_bfloat16 h[4], l[4];
            split2(v.x, h[0], l[0]); split2(v.y, h[1], l[1]);
            split2(v.z, h[2], l[2]); split2(v.w, h[3], l[3]);
            ph = make_uint2(pack_bf16(h[0], h[1]), pack_bf16(h[2], h[3]));
            pl = make_uint2(pack_bf16(l[0], l[1]), pack_bf16(l[2], l[3]));
        }
        ((uint2*)(hi + (size_t)b * NASPAD))[j] = ph;
        ((uint2*)(lo + (size_t)b * NASPAD))[j] = pl;
    }
}

// out[b] = dot(g_F[b,:], g_V[b,:]) / NASPECT
__global__ void __launch_bounds__(256)
final_dot(float* __restrict__ out)
{
    const int b = blockIdx.x;
    const float* f = g_F + (size_t)b * EMBED;
    const float* v = g_V + (size_t)b * EMBED;
    float s = 0.f;
    for (int i = threadIdx.x; i < EMBED; i += 256)
        s = fmaf(f[i], v[i], s);
    #pragma unroll
    for (int off = 16; off > 0; off >>= 1)
        s += __shfl_xor_sync(0xFFFFFFFFu, s, off);
    __shared__ float red[8];
    if ((threadIdx.x & 31) == 0) red[threadIdx.x >> 5] = s;
    __syncthreads();
    if (threadIdx.x < 8) {
        s = red[threadIdx.x];
        #pragma unroll
        for (int off = 4; off > 0; off >>= 1)
            s += __shfl_xor_sync(0xFFu, s, off);
        if (threadIdx.x == 0) out[b] = s * (1.0f / (float)NASPECT);
    }
}

// ---------------------------------------------------------------------------
#define SM_G1 (2 * (128 * (64 + 8) * 2 + 2 * 64 * (128 + 8) * 2))      // 106496
#define SM_G2 (2 * (2 * 64 * (64 + 8) * 2 + 2 * 64 * (64 + 8) * 2))    // 73728

extern "C" void kernel_launch(void* const* d_in, const int* in_sizes, int n_in,
                              void* d_out, int out_size)
{
    const float* image     = (const float*)d_in[0];
    const int*   brand     = (const int*)d_in[1];
    const float* W1        = (const float*)d_in[2];
    const float* b1        = (const float*)d_in[3];
    const float* W2        = (const float*)d_in[4];
    const float* b2        = (const float*)d_in[5];
    const float* brand_emb = (const float*)d_in[6];
    const float* aspects   = (const float*)d_in[7];
    float*       out       = (float*)d_out;

    static bool init = false;
    static __half *pImgF, *pW1H, *pW1L;
    static __nv_bfloat16 *pHH, *pHL, *pW2H, *pW2L, *pGH, *pGL, *pASH, *pASL;
    static float *pF, *pV;
    if (!init) {
        cudaGetSymbolAddress((void**)&pImgF, g_imgF);
        cudaGetSymbolAddress((void**)&pW1H,  g_W1H);
        cudaGetSymbolAddress((void**)&pW1L,  g_W1L);
        cudaGetSymbolAddress((void**)&pHH,   g_HH);
        cudaGetSymbolAddress((void**)&pHL,   g_HL);
        cudaGetSymbolAddress((void**)&pW2H,  g_W2H);
        cudaGetSymbolAddress((void**)&pW2L,  g_W2L);
        cudaGetSymbolAddress((void**)&pGH,   g_GH);
        cudaGetSymbolAddress((void**)&pGL,   g_GL);
        cudaGetSymbolAddress((void**)&pASH,  g_ASH);
        cudaGetSymbolAddress((void**)&pASL,  g_ASL);
        cudaGetSymbolAddress((void**)&pF,    g_F);
        cudaGetSymbolAddress((void**)&pV,    g_V);
        cudaFuncSetAttribute((const void*)gemm_f16x2<128,128,64,64,32>,
                             cudaFuncAttributeMaxDynamicSharedMemorySize, SM_G1);
        cudaFuncSetAttribute((const void*)gemm_mma<64,64,64,32,16,2>,
                             cudaFuncAttributeMaxDynamicSharedMemorySize, SM_G2);
        cudaFuncSetAttribute((const void*)gemm_mma<64,64,64,32,16,1>,
                             cudaFuncAttributeMaxDynamicSharedMemorySize, SM_G2);
        init = true;
    }

    // Operand conversions
    cast_half<<<(BATCH * FCIN / 4 + 255) / 256, 256>>>(image, pImgF, BATCH * FCIN / 4);
    split_half<<<(FCIN * FCIN / 4 + 255) / 256, 256>>>(W1, pW1H, pW1L, FCIN * FCIN / 4);
    split_pad<<<(FCIN * EMBED / 4 + 255) / 256, 256>>>(
        W2, pW2H, pW2L, FCIN * EMBED / 4, FCIN * EMBED / 4);
    split_pad<<<(NASPAD * EMBED / 4 + 255) / 256, 256>>>(
        aspects, pASH, pASL, NASPAD * EMBED / 4, NASPECT * EMBED / 4);
    gather_split<<<BATCH, 256>>>(brand_emb, brand, pGH, pGL);

    // GEMM1 (fp16 2-MMA): H = lrelu(image @ W1 + b1) -> bf16 hi/lo
    gemm_f16x2<128,128,64,64,32><<<dim3(FCIN / 128, BATCH / 128), 256, SM_G1>>>(
        pImgF, pW1H, pW1L, b1, FCIN, FCIN, FCIN, pHH, pHL);

    // GEMM3 (bf16 3-MMA): V = gather(brand_emb) @ aspects
    gemm_mma<64,64,64,32,16,2><<<dim3(EMBED / 64, BATCH / 64), 256, SM_G2>>>(
        pGH, pGL, pASH, pASL, nullptr, NASPAD, EMBED, EMBED, pV);

    // GEMM2 (bf16 3-MMA): F = H @ W2 + b2
    gemm_mma<64,64,64,32,16,1><<<dim3(EMBED / 64, BATCH / 64), 256, SM_G2>>>(
        pHH, pHL, pW2H, pW2L, b2, FCIN, EMBED, EMBED, pF);

    final_dot<<<BATCH, 256>>>(out);
}

// round 9
// speedup vs baseline: 4.0677x; 1.0847x over previous
#include <cuda_runtime.h>
#include <cuda_bf16.h>
#include <cuda_fp16.h>
#include <cstdint>

#define BATCH   512
#define FCIN    4096
#define EMBED   1024
#define NASPECT 2000
#define NASPAD  2048
#define NBRANDS 10000

// ---------------------------------------------------------------------------
// Scratch (__device__ globals). All GEMMs: A single fp16, B fp16 hi/lo.
// ---------------------------------------------------------------------------
__device__ __align__(256) __half g_imgF[BATCH * FCIN];
__device__ __align__(256) __half g_W1H[FCIN * FCIN];     // [K,N]
__device__ __align__(256) __half g_W1L[FCIN * FCIN];
__device__ __align__(256) __half g_Hf[BATCH * FCIN];     // lrelu out, fp16
__device__ __align__(256) __half g_W2H[FCIN * EMBED];    // [K,N]
__device__ __align__(256) __half g_W2L[FCIN * EMBED];
__device__ __align__(256) __half g_Gf[BATCH * NASPAD];   // gathered, fp16
__device__ __align__(256) __half g_ASH[NASPAD * EMBED];  // [Kpad,N]
__device__ __align__(256) __half g_ASL[NASPAD * EMBED];
__device__ __align__(256) float g_F[BATCH * EMBED];
__device__ __align__(256) float g_V[BATCH * EMBED];

// ---------------------------------------------------------------------------
// PTX helpers
// ---------------------------------------------------------------------------
__device__ __forceinline__ uint32_t smem_u32(const void* p) {
    uint32_t a;
    asm("{ .reg .u64 t; cvta.to.shared.u64 t, %1; cvt.u32.u64 %0, t; }"
        : "=r"(a) : "l"(p));
    return a;
}
__device__ __forceinline__ void ldsm4(uint32_t* r, uint32_t addr) {
    asm volatile("ldmatrix.sync.aligned.m8n8.x4.shared.b16 {%0,%1,%2,%3}, [%4];"
        : "=r"(r[0]), "=r"(r[1]), "=r"(r[2]), "=r"(r[3]) : "r"(addr));
}
__device__ __forceinline__ void ldsm2t(uint32_t* r, uint32_t addr) {
    asm volatile("ldmatrix.sync.aligned.m8n8.x2.trans.shared.b16 {%0,%1}, [%2];"
        : "=r"(r[0]), "=r"(r[1]) : "r"(addr));
}
__device__ __forceinline__ void mma_f16(float* d, const uint32_t* a, const uint32_t* b) {
    asm volatile("mma.sync.aligned.m16n8k16.row.col.f32.f16.f16.f32 "
        "{%0,%1,%2,%3}, {%4,%5,%6,%7}, {%8,%9}, {%0,%1,%2,%3};"
        : "+f"(d[0]), "+f"(d[1]), "+f"(d[2]), "+f"(d[3])
        : "r"(a[0]), "r"(a[1]), "r"(a[2]), "r"(a[3]), "r"(b[0]), "r"(b[1]));
}
__device__ __forceinline__ void cpa16(uint32_t d, const void* s) {
    asm volatile("cp.async.cg.shared.global [%0], [%1], 16;" :: "r"(d), "l"(s));
}
#define CPA_COMMIT() asm volatile("cp.async.commit_group;" ::: "memory")
#define CPA_WAIT(n)  asm volatile("cp.async.wait_group %0;" :: "n"(n) : "memory")

__device__ __forceinline__ void split2h(float x, __half& h, __half& l) {
    h = __float2half_rn(x);
    l = __float2half_rn(x - __half2float(h));
}
__device__ __forceinline__ uint32_t pack_f16(__half a, __half b) {
    return (uint32_t)*(uint16_t*)&a | ((uint32_t)*(uint16_t*)&b << 16);
}

// ---------------------------------------------------------------------------
// fp16 2-MMA split GEMM:  C = A·Bh + A·Bl
// A: [M,K] fp16 single. B: [K,N] fp16 hi/lo (ldmatrix.trans fragments).
// 8 warps (BM/WM x BN/WN), BK=64, cp.async double-buffered.
// EPI: 0 = +bias, lrelu, write fp16 (H); 1 = +bias fp32; 2 = fp32.
// ---------------------------------------------------------------------------
template<int BM, int BN, int BK, int WM, int WN, int EPI>
__global__ void __launch_bounds__(256)
gemm_f16x2(const __half* __restrict__ A,
           const __half* __restrict__ Bh, const __half* __restrict__ Bl,
           const float* __restrict__ bias, int K, int ldb, int ldc,
           float* __restrict__ Cf, __half* __restrict__ Ch)
{
    constexpr int SA = (BK + 8) * 2;
    constexpr int SB = (BN + 8) * 2;
    constexpr int OFF_A  = 0;
    constexpr int OFF_BH = BM * SA;
    constexpr int OFF_BL = BM * SA + BK * SB;
    constexpr int BUFB = BM * SA + 2 * BK * SB;
    constexpr int MI = WM / 16, NI = WN / 8;
    constexpr int KS = BK / 16;
    constexpr int AK8 = BK / 8;
    constexpr int BN8 = BN / 8;

    extern __shared__ __align__(128) char smem[];
    const uint32_t sb = smem_u32(smem);
    const int tid = threadIdx.x, wid = tid >> 5, lane = tid & 31;
    const int wm = wid % (BM / WM), wn = wid / (BM / WM);
    const int rowbase = blockIdx.y * BM, colbase = blockIdx.x * BN;

    const __half* srcA = A + (size_t)rowbase * K;
    const __half* srcB[2] = { Bh + colbase, Bl + colbase };

    float acc[MI][NI][4];
    #pragma unroll
    for (int i = 0; i < MI; i++)
        #pragma unroll
        for (int j = 0; j < NI; j++)
            #pragma unroll
            for (int q = 0; q < 4; q++) acc[i][j][q] = 0.f;

    const uint32_t aBase = (uint32_t)((wm * WM + (lane & 15)) * SA + (lane >> 4) * 16);
    const uint32_t bBase = (uint32_t)((lane & 15) * SB + (wn * WN) * 2);

    auto prefetch = [&](int chunk, int p) {
        const uint32_t tb = sb + p * BUFB;
        const int k0 = chunk * BK;
        #pragma unroll
        for (int i = tid; i < BM * AK8; i += 256) {
            int r = i / AK8, c = i % AK8;
            cpa16(tb + OFF_A + (uint32_t)(r * SA + c * 16),
                  srcA + (size_t)r * K + k0 + c * 8);
        }
        #pragma unroll
        for (int i = tid; i < BK * BN8; i += 256) {
            int r = i / BN8, c = i % BN8;
            uint32_t d = (uint32_t)(r * SB + c * 16);
            cpa16(tb + OFF_BH + d, srcB[0] + (size_t)(k0 + r) * ldb + c * 8);
            cpa16(tb + OFF_BL + d, srcB[1] + (size_t)(k0 + r) * ldb + c * 8);
        }
        CPA_COMMIT();
    };

    const int NC = K / BK;
    prefetch(0, 0);

    for (int c = 0; c < NC; c++) {
        const int p = c & 1;
        if (c + 1 < NC) { prefetch(c + 1, (c + 1) & 1); CPA_WAIT(1); }
        else            { CPA_WAIT(0); }
        __syncthreads();

        const uint32_t tb = sb + p * BUFB;
        #pragma unroll
        for (int ks = 0; ks < KS; ks++) {
            uint32_t aF[MI][4], bH[NI][2], bL[NI][2];
            #pragma unroll
            for (int mi = 0; mi < MI; mi++)
                ldsm4(aF[mi], tb + OFF_A + aBase + (uint32_t)(mi * 16 * SA + ks * 32));
            #pragma unroll
            for (int ni = 0; ni < NI; ni++) {
                uint32_t o = bBase + (uint32_t)(ks * 16 * SB + ni * 16);
                ldsm2t(bH[ni], tb + OFF_BH + o);
                ldsm2t(bL[ni], tb + OFF_BL + o);
            }
            #pragma unroll
            for (int mi = 0; mi < MI; mi++)
                #pragma unroll
                for (int ni = 0; ni < NI; ni++) {
                    mma_f16(acc[mi][ni], aF[mi], bH[ni]);
                    mma_f16(acc[mi][ni], aF[mi], bL[ni]);
                }
        }
        __syncthreads();
    }

    // Epilogue. Frag map: d0,d1 -> row lane>>2, cols (lane&3)*2,+1; d2,d3 -> +8 rows.
    const int r0 = rowbase + wm * WM + (lane >> 2);
    const int c0 = colbase + wn * WN + (lane & 3) * 2;
    #pragma unroll
    for (int mi = 0; mi < MI; mi++) {
        #pragma unroll
        for (int ni = 0; ni < NI; ni++) {
            const int cc = c0 + ni * 8;
            float b0 = 0.f, b1 = 0.f;
            if (EPI == 0 || EPI == 1) { b0 = __ldg(&bias[cc]); b1 = __ldg(&bias[cc + 1]); }
            #pragma unroll
            for (int h = 0; h < 2; h++) {
                const int rr = r0 + mi * 16 + h * 8;
                float v0 = acc[mi][ni][2 * h]     + b0;
                float v1 = acc[mi][ni][2 * h + 1] + b1;
                if (EPI == 0) {
                    v0 = v0 > 0.f ? v0 : 0.01f * v0;
                    v1 = v1 > 0.f ? v1 : 0.01f * v1;
                    *(uint32_t*)(Ch + (size_t)rr * ldc + cc) =
                        pack_f16(__float2half_rn(v0), __float2half_rn(v1));
                } else {
                    *(float2*)(Cf + (size_t)rr * ldc + cc) = make_float2(v0, v1);
                }
            }
        }
    }
}

// ---------------------------------------------------------------------------
// Conversion kernels: 4 independent float4s per thread (MLP=4), coalesced.
// ---------------------------------------------------------------------------
// fp32 -> fp16 cast. Grid must satisfy 4 * gridDim.x * 256 >= n4.
__global__ void __launch_bounds__(256)
cast4_half(const float* __restrict__ in, __half* __restrict__ o, int n4)
{
    const int t = blockIdx.x * 256 + threadIdx.x;
    const int NT = gridDim.x * 256;
    #pragma unroll
    for (int k = 0; k < 4; k++) {
        int i = t + k * NT;
        if (i < n4) {
            float4 v = ((const float4*)in)[i];
            ((uint2*)o)[i] = make_uint2(
                pack_f16(__float2half_rn(v.x), __float2half_rn(v.y)),
                pack_f16(__float2half_rn(v.z), __float2half_rn(v.w)));
        }
    }
}

// fp32 -> fp16 hi/lo split with zero suffix (valid4..total4 -> 0)
__global__ void __launch_bounds__(256)
split4_half(const float* __restrict__ in, __half* __restrict__ hi,
            __half* __restrict__ lo, int total4, int valid4)
{
    const int t = blockIdx.x * 256 + threadIdx.x;
    const int NT = gridDim.x * 256;
    #pragma unroll
    for (int k = 0; k < 4; k++) {
        int i = t + k * NT;
        if (i < total4) {
            uint2 ph = make_uint2(0, 0), pl = make_uint2(0, 0);
            if (i < valid4) {
                float4 v = ((const float4*)in)[i];
                __half h[4], l[4];
                split2h(v.x, h[0], l[0]); split2h(v.y, h[1], l[1]);
                split2h(v.z, h[2], l[2]); split2h(v.w, h[3], l[3]);
                ph = make_uint2(pack_f16(h[0], h[1]), pack_f16(h[2], h[3]));
                pl = make_uint2(pack_f16(l[0], l[1]), pack_f16(l[2], l[3]));
            }
            ((uint2*)hi)[i] = ph;
            ((uint2*)lo)[i] = pl;
        }
    }
}

// Gather brand rows -> fp16 single, pad cols to NASPAD
__global__ void __launch_bounds__(256)
gather_cast(const float* __restrict__ emb, const int* __restrict__ idx,
            __half* __restrict__ o)
{
    const int b = blockIdx.x;
    int row = idx[b];
    row = row < 0 ? 0 : (row >= NBRANDS ? NBRANDS - 1 : row);
    const float4* src = (const float4*)(emb + (size_t)row * NASPECT);
    for (int j = threadIdx.x; j < NASPAD / 4; j += 256) {
        uint2 p = make_uint2(0, 0);
        if (j < NASPECT / 4) {
            float4 v = src[j];
            p = make_uint2(pack_f16(__float2half_rn(v.x), __float2half_rn(v.y)),
                           pack_f16(__float2half_rn(v.z), __float2half_rn(v.w)));
        }
        ((uint2*)(o + (size_t)b * NASPAD))[j] = p;
    }
}

// out[b] = dot(g_F[b,:], g_V[b,:]) / NASPECT
__global__ void __launch_bounds__(256)
final_dot(float* __restrict__ out)
{
    const int b = blockIdx.x;
    const float* f = g_F + (size_t)b * EMBED;
    const float* v = g_V + (size_t)b * EMBED;
    float s = 0.f;
    for (int i = threadIdx.x; i < EMBED; i += 256)
        s = fmaf(f[i], v[i], s);
    #pragma unroll
    for (int off = 16; off > 0; off >>= 1)
        s += __shfl_xor_sync(0xFFFFFFFFu, s, off);
    __shared__ float red[8];
    if ((threadIdx.x & 31) == 0) red[threadIdx.x >> 5] = s;
    __syncthreads();
    if (threadIdx.x < 8) {
        s = red[threadIdx.x];
        #pragma unroll
        for (int off = 4; off > 0; off >>= 1)
            s += __shfl_xor_sync(0xFFu, s, off);
        if (threadIdx.x == 0) out[b] = s * (1.0f / (float)NASPECT);
    }
}

// ---------------------------------------------------------------------------
#define SM_G1 (2 * (128 * (64 + 8) * 2 + 2 * 64 * (128 + 8) * 2))   // 106496
#define SM_G2 (2 * (64 * (64 + 8) * 2 + 2 * 64 * (64 + 8) * 2))     // 55296
#define G4(n4) (((n4) + 4 * 256 - 1) / (4 * 256))

extern "C" void kernel_launch(void* const* d_in, const int* in_sizes, int n_in,
                              void* d_out, int out_size)
{
    const float* image     = (const float*)d_in[0];
    const int*   brand     = (const int*)d_in[1];
    const float* W1        = (const float*)d_in[2];
    const float* b1        = (const float*)d_in[3];
    const float* W2        = (const float*)d_in[4];
    const float* b2        = (const float*)d_in[5];
    const float* brand_emb = (const float*)d_in[6];
    const float* aspects   = (const float*)d_in[7];
    float*       out       = (float*)d_out;

    static bool init = false;
    static __half *pImgF, *pW1H, *pW1L, *pHf, *pW2H, *pW2L, *pGf, *pASH, *pASL;
    static float *pF, *pV;
    if (!init) {
        cudaGetSymbolAddress((void**)&pImgF, g_imgF);
        cudaGetSymbolAddress((void**)&pW1H,  g_W1H);
        cudaGetSymbolAddress((void**)&pW1L,  g_W1L);
        cudaGetSymbolAddress((void**)&pHf,   g_Hf);
        cudaGetSymbolAddress((void**)&pW2H,  g_W2H);
        cudaGetSymbolAddress((void**)&pW2L,  g_W2L);
        cudaGetSymbolAddress((void**)&pGf,   g_Gf);
        cudaGetSymbolAddress((void**)&pASH,  g_ASH);
        cudaGetSymbolAddress((void**)&pASL,  g_ASL);
        cudaGetSymbolAddress((void**)&pF,    g_F);
        cudaGetSymbolAddress((void**)&pV,    g_V);
        cudaFuncSetAttribute((const void*)gemm_f16x2<128,128,64,64,32,0>,
                             cudaFuncAttributeMaxDynamicSharedMemorySize, SM_G1);
        cudaFuncSetAttribute((const void*)gemm_f16x2<64,64,64,32,16,2>,
                             cudaFuncAttributeMaxDynamicSharedMemorySize, SM_G2);
        cudaFuncSetAttribute((const void*)gemm_f16x2<64,64,64,32,16,1>,
                             cudaFuncAttributeMaxDynamicSharedMemorySize, SM_G2);
        init = true;
    }

    // Operand conversions
    cast4_half<<<G4(BATCH * FCIN / 4), 256>>>(image, pImgF, BATCH * FCIN / 4);
    split4_half<<<G4(FCIN * FCIN / 4), 256>>>(
        W1, pW1H, pW1L, FCIN * FCIN / 4, FCIN * FCIN / 4);
    split4_half<<<G4(FCIN * EMBED / 4), 256>>>(
        W2, pW2H, pW2L, FCIN * EMBED / 4, FCIN * EMBED / 4);
    split4_half<<<G4(NASPAD * EMBED / 4), 256>>>(
        aspects, pASH, pASL, NASPAD * EMBED / 4, NASPECT * EMBED / 4);
    gather_cast<<<BATCH, 256>>>(brand_emb, brand, pGf);

    // GEMM1: H = lrelu(image @ W1 + b1) -> fp16
    gemm_f16x2<128,128,64,64,32,0><<<dim3(FCIN / 128, BATCH / 128), 256, SM_G1>>>(
        pImgF, pW1H, pW1L, b1, FCIN, FCIN, FCIN, nullptr, pHf);

    // GEMM3: V = gather(brand_emb) @ aspects -> fp32
    gemm_f16x2<64,64,64,32,16,2><<<dim3(EMBED / 64, BATCH / 64), 256, SM_G2>>>(
        pGf, pASH, pASL, nullptr, NASPAD, EMBED, EMBED, pV, nullptr);

    // GEMM2: F = H @ W2 + b2 -> fp32
    gemm_f16x2<64,64,64,32,16,1><<<dim3(EMBED / 64, BATCH / 64), 256, SM_G2>>>(
        pHf, pW2H, pW2L, b2, FCIN, EMBED, EMBED, pF, nullptr);

    final_dot<<<BATCH, 256>>>(out);
}